// round 7
// baseline (speedup 1.0000x reference)
#include <cuda_runtime.h>
#include <cstdint>

#define NNODES 50000
#define EEDGES 1600000
#define DHID 128
#define DNF 128
#define DNG 64
#define LN2 0.69314718055994530942f
#define FPI 3.14159265358979323846f

typedef unsigned long long ull;

// Scratch (static device arrays: allocation-free per harness rules)
__device__ float g_h[(size_t)NNODES * DNF];    // x @ lin1_w
__device__ float g_agg[(size_t)NNODES * DNF];  // segment_sum accumulator
__device__ int   g_cnt;                        // compacted edge count
__device__ int   g_eid[EEDGES];                // compacted: original edge id
__device__ int   g_src[EEDGES];
__device__ int   g_dst[EEDGES];
__device__ float g_C[EEDGES];                  // cutoff envelope

// ---------------- helpers ----------------
__device__ __forceinline__ float ssp_f(float v) {
    return fmaxf(v, 0.0f) + __logf(1.0f + __expf(-fabsf(v))) - LN2;
}
__device__ __forceinline__ void red_add_v4(float* p, float a, float b, float c, float d) {
    asm volatile("red.global.add.v4.f32 [%0], {%1, %2, %3, %4};"
                 :: "l"(p), "f"(a), "f"(b), "f"(c), "f"(d) : "memory");
}
__device__ __forceinline__ ull pack2(float a) {
    ull r;
    asm("mov.b64 %0, {%1, %1};" : "=l"(r) : "f"(a));
    return r;
}
__device__ __forceinline__ float2 unpack2(ull v) {
    float2 f;
    asm("mov.b64 {%0, %1}, %2;" : "=f"(f.x), "=f"(f.y) : "l"(v));
    return f;
}
__device__ __forceinline__ void fma2(ull& d, ull a, ull b) {
    asm("fma.rn.f32x2 %0, %1, %2, %0;" : "+l"(d) : "l"(a), "l"(b));
}
__device__ __forceinline__ float4 ldcs4(const float* p) {
    float4 v;
    asm volatile("ld.global.cs.v4.f32 {%0,%1,%2,%3}, [%4];"
                 : "=f"(v.x), "=f"(v.y), "=f"(v.z), "=f"(v.w) : "l"(p));
    return v;
}
__device__ __forceinline__ float4 ldcg4(const float* p) {
    float4 v;
    asm volatile("ld.global.cg.v4.f32 {%0,%1,%2,%3}, [%4];"
                 : "=f"(v.x), "=f"(v.y), "=f"(v.z), "=f"(v.w) : "l"(p));
    return v;
}

// 8x8 microkernel, 256 threads / 128x128 tile, B streamed from GLOBAL (L1-cached).
// cg = tid>>4 (c0=8cg), rg = tid&15 (row pairs rg2, +32, +64, +96).
// acc[j][c] = f32x2 row-pair. As: [k][row] stride 130. Bg: [k][col] stride 128.
template <int K>
__device__ __forceinline__ void mm8x8g(const float* __restrict__ As,
                                       const float* __restrict__ Bg,
                                       int rg2, int c0, ull acc[4][8]) {
#pragma unroll 4
    for (int k = 0; k < K; ++k) {
        const float* ar = As + k * 130 + rg2;
        ull a0 = *(const ull*)(ar);
        ull a1 = *(const ull*)(ar + 32);
        ull a2 = *(const ull*)(ar + 64);
        ull a3 = *(const ull*)(ar + 96);
        const float4* bp = (const float4*)(Bg + k * 128 + c0);
        float4 b0 = __ldg(bp);
        float4 b1 = __ldg(bp + 1);
        ull bb[8] = {pack2(b0.x), pack2(b0.y), pack2(b0.z), pack2(b0.w),
                     pack2(b1.x), pack2(b1.y), pack2(b1.z), pack2(b1.w)};
#pragma unroll
        for (int c = 0; c < 8; ++c) {
            fma2(acc[0][c], a0, bb[c]);
            fma2(acc[1][c], a1, bb[c]);
            fma2(acc[2][c], a2, bb[c]);
            fma2(acc[3][c], a3, bb[c]);
        }
    }
}

// smem-B variant (for k_out: weights resident in shared)
template <int K>
__device__ __forceinline__ void mm8x8s(const float* __restrict__ As,
                                       const float* __restrict__ Bs,
                                       int rg2, int c0, ull acc[4][8]) {
#pragma unroll 4
    for (int k = 0; k < K; ++k) {
        const float* ar = As + k * 130 + rg2;
        ull a0 = *(const ull*)(ar);
        ull a1 = *(const ull*)(ar + 32);
        ull a2 = *(const ull*)(ar + 64);
        ull a3 = *(const ull*)(ar + 96);
        const float* br = Bs + k * 128 + c0;
        float4 b0 = *(const float4*)br;
        float4 b1 = *(const float4*)(br + 4);
        ull bb[8] = {pack2(b0.x), pack2(b0.y), pack2(b0.z), pack2(b0.w),
                     pack2(b1.x), pack2(b1.y), pack2(b1.z), pack2(b1.w)};
#pragma unroll
        for (int c = 0; c < 8; ++c) {
            fma2(acc[0][c], a0, bb[c]);
            fma2(acc[1][c], a1, bb[c]);
            fma2(acc[2][c], a2, bb[c]);
            fma2(acc[3][c], a3, bb[c]);
        }
    }
}

__device__ __forceinline__ void zero_acc(ull acc[4][8]) {
#pragma unroll
    for (int j = 0; j < 4; ++j)
#pragma unroll
        for (int c = 0; c < 8; ++c) acc[j][c] = 0ull;
}

// ---------------- Kernel 0: compact edges with C != 0 ----------------
extern "C" __global__ void __launch_bounds__(256)
k_compact(const int* __restrict__ ei, const float* __restrict__ elen) {
    const int stride = gridDim.x * blockDim.x;
    const int i0 = blockIdx.x * blockDim.x + threadIdx.x;
    const int lane = threadIdx.x & 31;
    const int nit = (EEDGES + stride - 1) / stride;
    for (int it = 0; it < nit; ++it) {
        int i = i0 + it * stride;
        bool in = i < EEDGES;
        float L = in ? elen[i] : -1.0f;
        bool valid = in && (L <= 10.0f) && (L >= 0.0f);
        unsigned mask = __ballot_sync(0xffffffffu, valid);
        if (mask) {
            int leader = __ffs(mask) - 1;
            int base = 0;
            if (lane == leader) base = atomicAdd(&g_cnt, __popc(mask));
            base = __shfl_sync(0xffffffffu, base, leader);
            if (valid) {
                int pos = base + __popc(mask & ((1u << lane) - 1u));
                g_eid[pos] = i;
                g_src[pos] = ei[i];
                g_dst[pos] = ei[EEDGES + i];
                g_C[pos] = 0.5f * (__cosf(L * (FPI / 10.0f)) + 1.0f);
            }
        }
    }
}

// ---------------- Kernel 1: h = x @ lin1_w, zero g_agg + g_cnt ----------------
extern "C" __global__ void __launch_bounds__(256, 2)
k_proj_zero(const float* __restrict__ x, const float* __restrict__ w1) {
    extern __shared__ float sm[];
    float* sX = sm;                 // 128*130 transposed tile
    const int tid = threadIdx.x;
    const int cg = tid >> 4, rg = tid & 15;
    const int c0 = cg * 8, rg2 = rg * 2;

    if (blockIdx.x == 0 && tid == 0) g_cnt = 0;

    const int ntiles = (NNODES + 127) / 128;
    for (int tile = blockIdx.x; tile < ntiles; tile += gridDim.x) {
        const int r0 = tile * 128;
        __syncthreads();
        {
            int e = tid >> 1, k0 = (tid & 1) << 6;
            int r = r0 + e;
            if (r < NNODES) {
                const float* src = x + (size_t)r * DHID + k0;
#pragma unroll
                for (int i = 0; i < 16; ++i) {
                    float4 v = ldcs4(src + 4 * i);
                    int k = k0 + 4 * i;
                    sX[(k + 0) * 130 + e] = v.x;
                    sX[(k + 1) * 130 + e] = v.y;
                    sX[(k + 2) * 130 + e] = v.z;
                    sX[(k + 3) * 130 + e] = v.w;
                }
            }
        }
        __syncthreads();
        ull acc[4][8];
        zero_acc(acc);
        mm8x8g<DHID>(sX, w1, rg2, c0, acc);
#pragma unroll
        for (int j = 0; j < 4; ++j) {
            int r = r0 + rg2 + 32 * j;
            float2 v0 = unpack2(acc[j][0]), v1 = unpack2(acc[j][1]);
            float2 v2 = unpack2(acc[j][2]), v3 = unpack2(acc[j][3]);
            float2 v4 = unpack2(acc[j][4]), v5 = unpack2(acc[j][5]);
            float2 v6 = unpack2(acc[j][6]), v7 = unpack2(acc[j][7]);
            if (r < NNODES) {
                *(float4*)(g_h + (size_t)r * DNF + c0) = make_float4(v0.x, v1.x, v2.x, v3.x);
                *(float4*)(g_h + (size_t)r * DNF + c0 + 4) = make_float4(v4.x, v5.x, v6.x, v7.x);
                *(float4*)(g_agg + (size_t)r * DNF + c0) = make_float4(0.f, 0.f, 0.f, 0.f);
                *(float4*)(g_agg + (size_t)r * DNF + c0 + 4) = make_float4(0.f, 0.f, 0.f, 0.f);
            }
            if (r + 1 < NNODES) {
                *(float4*)(g_h + (size_t)(r + 1) * DNF + c0) = make_float4(v0.y, v1.y, v2.y, v3.y);
                *(float4*)(g_h + (size_t)(r + 1) * DNF + c0 + 4) = make_float4(v4.y, v5.y, v6.y, v7.y);
                *(float4*)(g_agg + (size_t)(r + 1) * DNF + c0) = make_float4(0.f, 0.f, 0.f, 0.f);
                *(float4*)(g_agg + (size_t)(r + 1) * DNF + c0 + 4) = make_float4(0.f, 0.f, 0.f, 0.f);
            }
        }
    }
}

// ---------------- Kernel 2: pipelined edge MLP + gather/scatter ----------------
// Separate sA/sT buffers; next tile's LDGs issued between GEMM1 and the ssp/STS phase
// so DRAM latency overlaps with MUFU work + GEMM2 instead of serializing.
extern "C" __global__ void __launch_bounds__(256, 2)
k_edge(const float* __restrict__ edge_attr,
       const float* __restrict__ w1, const float* __restrict__ b1,
       const float* __restrict__ w2, const float* __restrict__ b2) {
    extern __shared__ float sm[];
    float* sA = sm;                        // 64*130
    float* sT = sA + DNG * 130;            // 128*130
    float* sC = sT + DNF * 130;            // 2*128 (double-buffered meta)
    int* sSrc = (int*)(sC + 256);          // 2*128
    int* sDst = sSrc + 256;                // 2*128

    const int tid = threadIdx.x;
    const int cg = tid >> 4, rg = tid & 15;
    const int c0 = cg * 8, rg2 = rg * 2;
    const int e = tid >> 1, g0 = (tid & 1) << 5;  // tile-load mapping

    const int cnt = g_cnt;
    const int ntiles = (cnt + 127) >> 7;
    const int stride = gridDim.x;

    // prologue: load first tile into sA + meta buf 0
    int tile = blockIdx.x;
    if (tile < ntiles) {
        int gi = (tile << 7) + e;
        int eid = (gi < cnt) ? g_eid[gi] : 0;
        const float* src = edge_attr + (size_t)eid * DNG + g0;
#pragma unroll
        for (int i = 0; i < 8; ++i) {
            float4 v = ldcs4(src + 4 * i);
            int g = g0 + 4 * i;
            sA[(g + 0) * 130 + e] = v.x;
            sA[(g + 1) * 130 + e] = v.y;
            sA[(g + 2) * 130 + e] = v.z;
            sA[(g + 3) * 130 + e] = v.w;
        }
        if ((tid & 1) == 0) {
            if (gi < cnt) { sC[e] = g_C[gi]; sSrc[e] = g_src[gi]; sDst[e] = g_dst[gi]; }
            else sC[e] = 0.0f;
        }
    }

    int par = 0;
    for (; tile < ntiles; tile += stride, par ^= 1) {
        __syncthreads();   // sA + meta[par] visible; sT free (prev GEMM2 done)

        ull acc[4][8];
        zero_acc(acc);
        mm8x8g<DNG>(sA, w1, rg2, c0, acc);   // T = A @ W1
        __syncthreads();   // all reads of sA complete -> safe to overwrite

        // --- prefetch next tile (LDG issue; latency hidden behind ssp phase) ---
        const int nt = tile + stride;
        const bool have = nt < ntiles;
        const int gi2 = (nt << 7) + e;
        float4 pf[8];
        float nC = 0.0f;
        int nS = 0, nD = 0;
        if (have) {
            int eid2 = (gi2 < cnt) ? g_eid[gi2] : 0;
            const float* src = edge_attr + (size_t)eid2 * DNG + g0;
#pragma unroll
            for (int i = 0; i < 8; ++i) pf[i] = ldcs4(src + 4 * i);
            if ((tid & 1) == 0 && gi2 < cnt) { nC = g_C[gi2]; nS = g_src[gi2]; nD = g_dst[gi2]; }
        }

        // --- ssp(T + b1) -> sT transposed (MUFU-heavy; overlaps prefetch latency) ---
        {
            float4 bA = __ldg((const float4*)(b1 + c0));
            float4 bB = __ldg((const float4*)(b1 + c0 + 4));
            float bv[8] = {bA.x, bA.y, bA.z, bA.w, bB.x, bB.y, bB.z, bB.w};
#pragma unroll
            for (int c = 0; c < 8; ++c) {
#pragma unroll
                for (int j = 0; j < 4; ++j) {
                    float2 v = unpack2(acc[j][c]);
                    *(float2*)(sT + (c0 + c) * 130 + rg2 + 32 * j) =
                        make_float2(ssp_f(v.x + bv[c]), ssp_f(v.y + bv[c]));
                }
            }
        }

        // --- store prefetched tile into sA + meta[par^1] ---
        if (have) {
#pragma unroll
            for (int i = 0; i < 8; ++i) {
                int g = g0 + 4 * i;
                sA[(g + 0) * 130 + e] = pf[i].x;
                sA[(g + 1) * 130 + e] = pf[i].y;
                sA[(g + 2) * 130 + e] = pf[i].z;
                sA[(g + 3) * 130 + e] = pf[i].w;
            }
            if ((tid & 1) == 0) {
                int q = (par ^ 1) * 128 + e;
                sC[q] = (gi2 < cnt) ? nC : 0.0f;
                sSrc[q] = nS;
                sDst[q] = nD;
            }
        }
        __syncthreads();   // sT ready

        zero_acc(acc);
        mm8x8g<DNF>(sT, w2, rg2, c0, acc);   // Wmat = ssp(T) @ W2

        // --- epilogue: msg = (Wmat + b2)*C*h[src]; scatter-add to agg[dst] ---
        float4 bA = __ldg((const float4*)(b2 + c0));
        float4 bB = __ldg((const float4*)(b2 + c0 + 4));
        const int q = par * 128;
#pragma unroll
        for (int j = 0; j < 4; ++j) {
            int el = rg2 + 32 * j;
            float2 v0 = unpack2(acc[j][0]), v1 = unpack2(acc[j][1]);
            float2 v2 = unpack2(acc[j][2]), v3 = unpack2(acc[j][3]);
            float2 v4 = unpack2(acc[j][4]), v5 = unpack2(acc[j][5]);
            float2 v6 = unpack2(acc[j][6]), v7 = unpack2(acc[j][7]);
            float cv0 = sC[q + el], cv1 = sC[q + el + 1];
            if (cv0 != 0.0f) {
                const float* hp = g_h + (size_t)sSrc[q + el] * DNF + c0;
                float4 h0 = ldcg4(hp);
                float4 h1 = ldcg4(hp + 4);
                float* dp = g_agg + (size_t)sDst[q + el] * DNF + c0;
                red_add_v4(dp, (v0.x + bA.x) * cv0 * h0.x, (v1.x + bA.y) * cv0 * h0.y,
                               (v2.x + bA.z) * cv0 * h0.z, (v3.x + bA.w) * cv0 * h0.w);
                red_add_v4(dp + 4, (v4.x + bB.x) * cv0 * h1.x, (v5.x + bB.y) * cv0 * h1.y,
                                   (v6.x + bB.z) * cv0 * h1.z, (v7.x + bB.w) * cv0 * h1.w);
            }
            if (cv1 != 0.0f) {
                const float* hp = g_h + (size_t)sSrc[q + el + 1] * DNF + c0;
                float4 h0 = ldcg4(hp);
                float4 h1 = ldcg4(hp + 4);
                float* dp = g_agg + (size_t)sDst[q + el + 1] * DNF + c0;
                red_add_v4(dp, (v0.y + bA.x) * cv1 * h0.x, (v1.y + bA.y) * cv1 * h0.y,
                               (v2.y + bA.z) * cv1 * h0.z, (v3.y + bA.w) * cv1 * h0.w);
                red_add_v4(dp + 4, (v4.y + bB.x) * cv1 * h1.x, (v5.y + bB.y) * cv1 * h1.y,
                                   (v6.y + bB.z) * cv1 * h1.z, (v7.y + bB.w) * cv1 * h1.w);
            }
        }
    }
}

// -------- Kernel 3: out = ssp(agg@lin2_w + lin2_b) @ lin_w + lin_b (smem weights) --------
extern "C" __global__ void __launch_bounds__(256, 1)
k_out(const float* __restrict__ w2, const float* __restrict__ b2,
      const float* __restrict__ w3, const float* __restrict__ b3,
      float* __restrict__ out) {
    extern __shared__ float sm[];
    float* sW2 = sm;                  // 128*128 (lin2_w)
    float* sW3 = sW2 + DNF * DHID;    // 128*128 (lin_w)
    float* sA  = sW3 + DHID * DHID;   // 128*130 (aliased A then T)
    float* sB2 = sA + DNF * 130;      // 128
    float* sB3 = sB2 + 128;           // 128

    const int tid = threadIdx.x;
    const int cg = tid >> 4, rg = tid & 15;
    const int c0 = cg * 8, rg2 = rg * 2;

    for (int i = tid; i < DNF * DHID / 4; i += 256)
        ((float4*)sW2)[i] = ((const float4*)w2)[i];
    for (int i = tid; i < DHID * DHID / 4; i += 256)
        ((float4*)sW3)[i] = ((const float4*)w3)[i];
    if (tid < DHID) { sB2[tid] = b2[tid]; sB3[tid] = b3[tid]; }

    const int ntiles = (NNODES + 127) / 128;
    for (int tile = blockIdx.x; tile < ntiles; tile += gridDim.x) {
        const int r0 = tile * 128;
        __syncthreads();
        {
            int e = tid >> 1, k0 = (tid & 1) << 6;
            int r = r0 + e;
            if (r < NNODES) {
                const float* src = g_agg + (size_t)r * DNF + k0;
#pragma unroll
                for (int i = 0; i < 16; ++i) {
                    float4 v = ldcs4(src + 4 * i);
                    int k = k0 + 4 * i;
                    sA[(k + 0) * 130 + e] = v.x;
                    sA[(k + 1) * 130 + e] = v.y;
                    sA[(k + 2) * 130 + e] = v.z;
                    sA[(k + 3) * 130 + e] = v.w;
                }
            } else {
#pragma unroll
                for (int i = 0; i < 16; ++i) {
                    int k = k0 + 4 * i;
                    sA[(k + 0) * 130 + e] = 0.f;
                    sA[(k + 1) * 130 + e] = 0.f;
                    sA[(k + 2) * 130 + e] = 0.f;
                    sA[(k + 3) * 130 + e] = 0.f;
                }
            }
        }
        __syncthreads();

        ull acc[4][8];
        zero_acc(acc);
        mm8x8s<DNF>(sA, sW2, rg2, c0, acc);
        __syncthreads();   // all reads of sA done before overwrite as T

        {
#pragma unroll
            for (int c = 0; c < 8; ++c) {
                float bv = sB2[c0 + c];
#pragma unroll
                for (int j = 0; j < 4; ++j) {
                    float2 v = unpack2(acc[j][c]);
                    *(float2*)(sA + (c0 + c) * 130 + rg2 + 32 * j) =
                        make_float2(ssp_f(v.x + bv), ssp_f(v.y + bv));
                }
            }
        }
        __syncthreads();

        zero_acc(acc);
        mm8x8s<DHID>(sA, sW3, rg2, c0, acc);

#pragma unroll
        for (int j = 0; j < 4; ++j) {
            int r = r0 + rg2 + 32 * j;
            float2 v0 = unpack2(acc[j][0]), v1 = unpack2(acc[j][1]);
            float2 v2 = unpack2(acc[j][2]), v3 = unpack2(acc[j][3]);
            float2 v4 = unpack2(acc[j][4]), v5 = unpack2(acc[j][5]);
            float2 v6 = unpack2(acc[j][6]), v7 = unpack2(acc[j][7]);
            if (r < NNODES) {
                *(float4*)(out + (size_t)r * DHID + c0) =
                    make_float4(v0.x + sB3[c0 + 0], v1.x + sB3[c0 + 1],
                                v2.x + sB3[c0 + 2], v3.x + sB3[c0 + 3]);
                *(float4*)(out + (size_t)r * DHID + c0 + 4) =
                    make_float4(v4.x + sB3[c0 + 4], v5.x + sB3[c0 + 5],
                                v6.x + sB3[c0 + 6], v7.x + sB3[c0 + 7]);
            }
            if (r + 1 < NNODES) {
                *(float4*)(out + (size_t)(r + 1) * DHID + c0) =
                    make_float4(v0.y + sB3[c0 + 0], v1.y + sB3[c0 + 1],
                                v2.y + sB3[c0 + 2], v3.y + sB3[c0 + 3]);
                *(float4*)(out + (size_t)(r + 1) * DHID + c0 + 4) =
                    make_float4(v4.y + sB3[c0 + 4], v5.y + sB3[c0 + 5],
                                v6.y + sB3[c0 + 6], v7.y + sB3[c0 + 7]);
            }
        }
    }
}

extern "C" void kernel_launch(void* const* d_in, const int* in_sizes, int n_in,
                              void* d_out, int out_size) {
    const float* x      = (const float*)d_in[0];
    const int*   ei     = (const int*)d_in[1];
    const float* elen   = (const float*)d_in[2];
    const float* eattr  = (const float*)d_in[3];
    const float* lin1_w = (const float*)d_in[4];
    const float* nn_w1  = (const float*)d_in[5];
    const float* nn_b1  = (const float*)d_in[6];
    const float* nn_w2  = (const float*)d_in[7];
    const float* nn_b2  = (const float*)d_in[8];
    const float* lin2_w = (const float*)d_in[9];
    const float* lin2_b = (const float*)d_in[10];
    const float* lin_w  = (const float*)d_in[11];
    const float* lin_b  = (const float*)d_in[12];
    float* out = (float*)d_out;

    size_t sm1 = (size_t)(DHID * 130) * 4;                            // 66560
    size_t sm2 = (size_t)(DNG * 130 + DNF * 130 + 6 * 128) * 4;       // 102912
    size_t sm3 = (size_t)(DNF * DHID + DHID * DHID + DNF * 130 + 2 * 128) * 4;  // 198656

    cudaFuncSetAttribute(k_proj_zero, cudaFuncAttributeMaxDynamicSharedMemorySize, (int)sm1);
    cudaFuncSetAttribute(k_edge, cudaFuncAttributeMaxDynamicSharedMemorySize, (int)sm2);
    cudaFuncSetAttribute(k_out, cudaFuncAttributeMaxDynamicSharedMemorySize, (int)sm3);

    k_proj_zero<<<304, 256, sm1>>>(x, lin1_w);          // also zeroes g_cnt + g_agg
    k_compact<<<152, 256>>>(ei, elen);
    k_edge<<<304, 256, sm2>>>(eattr, nn_w1, nn_b1, nn_w2, nn_b2);
    k_out<<<152, 256, sm3>>>(lin2_w, lin2_b, lin_w, lin_b, out);
}

// round 8
// speedup vs baseline: 1.1461x; 1.1461x over previous
#include <cuda_runtime.h>
#include <cstdint>

#define NNODES 50000
#define EEDGES 1600000
#define DHID 128
#define DNF 128
#define DNG 64
#define LN2 0.69314718055994530942f
#define FPI 3.14159265358979323846f

typedef unsigned long long ull;

// Scratch (static device arrays: allocation-free per harness rules)
__device__ float g_h[(size_t)NNODES * DNF];    // x @ lin1_w
__device__ float g_agg[(size_t)NNODES * DNF];  // segment_sum accumulator
__device__ int   g_cnt;                        // compacted edge count
__device__ int   g_eid[EEDGES + 128];          // compacted: original edge id (padded for tail reads)
__device__ int   g_src[EEDGES + 128];
__device__ int   g_dst[EEDGES + 128];
__device__ float g_C[EEDGES + 128];            // cutoff envelope

// ---------------- helpers ----------------
__device__ __forceinline__ float ssp_f(float v) {
    return fmaxf(v, 0.0f) + __logf(1.0f + __expf(-fabsf(v))) - LN2;
}
__device__ __forceinline__ void red_add_v4(float* p, float a, float b, float c, float d) {
    asm volatile("red.global.add.v4.f32 [%0], {%1, %2, %3, %4};"
                 :: "l"(p), "f"(a), "f"(b), "f"(c), "f"(d) : "memory");
}
__device__ __forceinline__ ull pack2(float a) {
    ull r;
    asm("mov.b64 %0, {%1, %1};" : "=l"(r) : "f"(a));
    return r;
}
__device__ __forceinline__ float2 unpack2(ull v) {
    float2 f;
    asm("mov.b64 {%0, %1}, %2;" : "=f"(f.x), "=f"(f.y) : "l"(v));
    return f;
}
__device__ __forceinline__ void fma2(ull& d, ull a, ull b) {
    asm("fma.rn.f32x2 %0, %1, %2, %0;" : "+l"(d) : "l"(a), "l"(b));
}
__device__ __forceinline__ float4 ldcs4(const float* p) {
    float4 v;
    asm volatile("ld.global.cs.v4.f32 {%0,%1,%2,%3}, [%4];"
                 : "=f"(v.x), "=f"(v.y), "=f"(v.z), "=f"(v.w) : "l"(p));
    return v;
}
__device__ __forceinline__ float4 ldcg4(const float* p) {
    float4 v;
    asm volatile("ld.global.cg.v4.f32 {%0,%1,%2,%3}, [%4];"
                 : "=f"(v.x), "=f"(v.y), "=f"(v.z), "=f"(v.w) : "l"(p));
    return v;
}

// 8x8 microkernel, 256 threads / 128x128 tile, B streamed from GLOBAL (L1-resident).
// cg = tid>>4 (c0=8cg), rg = tid&15 (row pairs rg2, +32, +64, +96).
// acc[j][c] = f32x2 row-pair. As: [k][row] stride 130. Bg: [k][col] stride 128.
template <int K>
__device__ __forceinline__ void mm8x8g(const float* __restrict__ As,
                                       const float* __restrict__ Bg,
                                       int rg2, int c0, ull acc[4][8]) {
#pragma unroll 4
    for (int k = 0; k < K; ++k) {
        const float* ar = As + k * 130 + rg2;
        ull a0 = *(const ull*)(ar);
        ull a1 = *(const ull*)(ar + 32);
        ull a2 = *(const ull*)(ar + 64);
        ull a3 = *(const ull*)(ar + 96);
        const float4* bp = (const float4*)(Bg + k * 128 + c0);
        float4 b0 = __ldg(bp);
        float4 b1 = __ldg(bp + 1);
        ull bb[8] = {pack2(b0.x), pack2(b0.y), pack2(b0.z), pack2(b0.w),
                     pack2(b1.x), pack2(b1.y), pack2(b1.z), pack2(b1.w)};
#pragma unroll
        for (int c = 0; c < 8; ++c) {
            fma2(acc[0][c], a0, bb[c]);
            fma2(acc[1][c], a1, bb[c]);
            fma2(acc[2][c], a2, bb[c]);
            fma2(acc[3][c], a3, bb[c]);
        }
    }
}

__device__ __forceinline__ void zero_acc8(ull acc[4][8]) {
#pragma unroll
    for (int j = 0; j < 4; ++j)
#pragma unroll
        for (int c = 0; c < 8; ++c) acc[j][c] = 0ull;
}

// 4x8 microkernel for k_out (512 threads, weights in smem) -- R5 shape, measured fastest there.
template <int K>
__device__ __forceinline__ void mm4x8(const float* __restrict__ As,
                                      const float* __restrict__ Bs,
                                      int rg, int c0, ull acc[4][4]) {
#pragma unroll 4
    for (int k = 0; k < K; ++k) {
        const float* ar = As + k * 130 + rg;
        ull a0 = pack2(ar[0]);
        ull a1 = pack2(ar[32]);
        ull a2 = pack2(ar[64]);
        ull a3 = pack2(ar[96]);
        const float* br = Bs + k * 128 + c0;
        ulonglong2 b01 = *(const ulonglong2*)br;
        ulonglong2 b23 = *(const ulonglong2*)(br + 4);
        ull bb[4] = {b01.x, b01.y, b23.x, b23.y};
#pragma unroll
        for (int p = 0; p < 4; ++p) {
            fma2(acc[0][p], a0, bb[p]);
            fma2(acc[1][p], a1, bb[p]);
            fma2(acc[2][p], a2, bb[p]);
            fma2(acc[3][p], a3, bb[p]);
        }
    }
}

// ---------------- Kernel 0: compact edges with C != 0 ----------------
extern "C" __global__ void __launch_bounds__(256)
k_compact(const int* __restrict__ ei, const float* __restrict__ elen) {
    const int stride = gridDim.x * blockDim.x;
    const int i0 = blockIdx.x * blockDim.x + threadIdx.x;
    const int lane = threadIdx.x & 31;
    const int nit = (EEDGES + stride - 1) / stride;
    for (int it = 0; it < nit; ++it) {
        int i = i0 + it * stride;
        bool in = i < EEDGES;
        float L = in ? elen[i] : -1.0f;
        bool valid = in && (L <= 10.0f) && (L >= 0.0f);
        unsigned mask = __ballot_sync(0xffffffffu, valid);
        if (mask) {
            int leader = __ffs(mask) - 1;
            int base = 0;
            if (lane == leader) base = atomicAdd(&g_cnt, __popc(mask));
            base = __shfl_sync(0xffffffffu, base, leader);
            if (valid) {
                int pos = base + __popc(mask & ((1u << lane) - 1u));
                g_eid[pos] = i;
                g_src[pos] = ei[i];
                g_dst[pos] = ei[EEDGES + i];
                g_C[pos] = 0.5f * (__cosf(L * (FPI / 10.0f)) + 1.0f);
            }
        }
    }
}

// ---------------- Kernel 1: h = x @ lin1_w, zero g_agg + g_cnt ----------------
extern "C" __global__ void __launch_bounds__(256, 2)
k_proj_zero(const float* __restrict__ x, const float* __restrict__ w1) {
    extern __shared__ float sm[];
    float* sX = sm;                 // 128*130 transposed tile = 66560 B
    const int tid = threadIdx.x;
    const int cg = tid >> 4, rg = tid & 15;
    const int c0 = cg * 8, rg2 = rg * 2;

    if (blockIdx.x == 0 && tid == 0) g_cnt = 0;

    const int ntiles = (NNODES + 127) / 128;
    for (int tile = blockIdx.x; tile < ntiles; tile += gridDim.x) {
        const int r0 = tile * 128;
        __syncthreads();
        {
            int e = tid >> 1, k0 = (tid & 1) << 6;
            int r = r0 + e;
            if (r < NNODES) {
                const float* src = x + (size_t)r * DHID + k0;
#pragma unroll
                for (int i = 0; i < 16; ++i) {
                    float4 v = ldcs4(src + 4 * i);
                    int k = k0 + 4 * i;
                    sX[(k + 0) * 130 + e] = v.x;
                    sX[(k + 1) * 130 + e] = v.y;
                    sX[(k + 2) * 130 + e] = v.z;
                    sX[(k + 3) * 130 + e] = v.w;
                }
            }
        }
        __syncthreads();
        ull acc[4][8];
        zero_acc8(acc);
        mm8x8g<DHID>(sX, w1, rg2, c0, acc);
#pragma unroll
        for (int j = 0; j < 4; ++j) {
            int r = r0 + rg2 + 32 * j;
            float2 v0 = unpack2(acc[j][0]), v1 = unpack2(acc[j][1]);
            float2 v2 = unpack2(acc[j][2]), v3 = unpack2(acc[j][3]);
            float2 v4 = unpack2(acc[j][4]), v5 = unpack2(acc[j][5]);
            float2 v6 = unpack2(acc[j][6]), v7 = unpack2(acc[j][7]);
            if (r < NNODES) {
                *(float4*)(g_h + (size_t)r * DNF + c0) = make_float4(v0.x, v1.x, v2.x, v3.x);
                *(float4*)(g_h + (size_t)r * DNF + c0 + 4) = make_float4(v4.x, v5.x, v6.x, v7.x);
                *(float4*)(g_agg + (size_t)r * DNF + c0) = make_float4(0.f, 0.f, 0.f, 0.f);
                *(float4*)(g_agg + (size_t)r * DNF + c0 + 4) = make_float4(0.f, 0.f, 0.f, 0.f);
            }
            if (r + 1 < NNODES) {
                *(float4*)(g_h + (size_t)(r + 1) * DNF + c0) = make_float4(v0.y, v1.y, v2.y, v3.y);
                *(float4*)(g_h + (size_t)(r + 1) * DNF + c0 + 4) = make_float4(v4.y, v5.y, v6.y, v7.y);
                *(float4*)(g_agg + (size_t)(r + 1) * DNF + c0) = make_float4(0.f, 0.f, 0.f, 0.f);
                *(float4*)(g_agg + (size_t)(r + 1) * DNF + c0 + 4) = make_float4(0.f, 0.f, 0.f, 0.f);
            }
        }
    }
}

// ---------------- Kernel 2: edge MLP + gather/scatter over compacted edges ----------------
// smem = ONLY the 128x130 tile union (66560 B) so 2 CTAs fit the 132KB carveout,
// leaving 96KB L1D for the resident W1+W2 (96KB). Edge meta read from global in epilogue.
extern "C" __global__ void __launch_bounds__(256, 2)
k_edge(const float* __restrict__ edge_attr,
       const float* __restrict__ w1, const float* __restrict__ b1,
       const float* __restrict__ w2, const float* __restrict__ b2) {
    extern __shared__ float sm[];
    float* sTile = sm;     // union: sA (first 64 rows) / sT (128 rows), stride 130

    const int tid = threadIdx.x;
    const int cg = tid >> 4, rg = tid & 15;
    const int c0 = cg * 8, rg2 = rg * 2;

    const int cnt = g_cnt;
    const int ntiles = (cnt + 127) >> 7;
    for (int tile = blockIdx.x; tile < ntiles; tile += gridDim.x) {
        const int eg0 = tile << 7;
        __syncthreads();   // prev tile GEMM2 done with sT
        {
            int e = tid >> 1, g0 = (tid & 1) << 5;
            int gi = eg0 + e;
            int eid = (gi < cnt) ? g_eid[gi] : 0;
            const float* src = edge_attr + (size_t)eid * DNG + g0;
#pragma unroll
            for (int i = 0; i < 8; ++i) {
                float4 v = ldcs4(src + 4 * i);
                int g = g0 + 4 * i;
                sTile[(g + 0) * 130 + e] = v.x;
                sTile[(g + 1) * 130 + e] = v.y;
                sTile[(g + 2) * 130 + e] = v.z;
                sTile[(g + 3) * 130 + e] = v.w;
            }
        }
        __syncthreads();

        ull acc[4][8];
        zero_acc8(acc);
        mm8x8g<DNG>(sTile, w1, rg2, c0, acc);   // T = A @ W1
        __syncthreads();   // all reads of sA done before overwriting as sT

        // ssp(T + b1) -> sT transposed (STS.64 row-pairs)
        {
            float4 bA = __ldg((const float4*)(b1 + c0));
            float4 bB = __ldg((const float4*)(b1 + c0 + 4));
            float bv[8] = {bA.x, bA.y, bA.z, bA.w, bB.x, bB.y, bB.z, bB.w};
#pragma unroll
            for (int c = 0; c < 8; ++c) {
#pragma unroll
                for (int j = 0; j < 4; ++j) {
                    float2 v = unpack2(acc[j][c]);
                    *(float2*)(sTile + (c0 + c) * 130 + rg2 + 32 * j) =
                        make_float2(ssp_f(v.x + bv[c]), ssp_f(v.y + bv[c]));
                }
            }
        }
        __syncthreads();

        zero_acc8(acc);
        mm8x8g<DNF>(sTile, w2, rg2, c0, acc);   // Wmat = ssp(T) @ W2

        // epilogue: msg = (Wmat + b2)*C*h[src]; scatter-add to agg[dst].
        // Edge meta straight from global (paired 8B loads; arrays padded past cnt).
        float4 bA = __ldg((const float4*)(b2 + c0));
        float4 bB = __ldg((const float4*)(b2 + c0 + 4));
#pragma unroll
        for (int j = 0; j < 4; ++j) {
            int el = rg2 + 32 * j;
            int gi = eg0 + el;
            float2 cv = __ldg((const float2*)(g_C + gi));
            int2 srcp = __ldg((const int2*)(g_src + gi));
            int2 dstp = __ldg((const int2*)(g_dst + gi));
            float2 v0 = unpack2(acc[j][0]), v1 = unpack2(acc[j][1]);
            float2 v2 = unpack2(acc[j][2]), v3 = unpack2(acc[j][3]);
            float2 v4 = unpack2(acc[j][4]), v5 = unpack2(acc[j][5]);
            float2 v6 = unpack2(acc[j][6]), v7 = unpack2(acc[j][7]);
            if (gi < cnt && cv.x != 0.0f) {
                const float* hp = g_h + (size_t)srcp.x * DNF + c0;
                float4 h0 = ldcg4(hp);
                float4 h1 = ldcg4(hp + 4);
                float* dp = g_agg + (size_t)dstp.x * DNF + c0;
                red_add_v4(dp, (v0.x + bA.x) * cv.x * h0.x, (v1.x + bA.y) * cv.x * h0.y,
                               (v2.x + bA.z) * cv.x * h0.z, (v3.x + bA.w) * cv.x * h0.w);
                red_add_v4(dp + 4, (v4.x + bB.x) * cv.x * h1.x, (v5.x + bB.y) * cv.x * h1.y,
                                   (v6.x + bB.z) * cv.x * h1.z, (v7.x + bB.w) * cv.x * h1.w);
            }
            if (gi + 1 < cnt && cv.y != 0.0f) {
                const float* hp = g_h + (size_t)srcp.y * DNF + c0;
                float4 h0 = ldcg4(hp);
                float4 h1 = ldcg4(hp + 4);
                float* dp = g_agg + (size_t)dstp.y * DNF + c0;
                red_add_v4(dp, (v0.y + bA.x) * cv.y * h0.x, (v1.y + bA.y) * cv.y * h0.y,
                               (v2.y + bA.z) * cv.y * h0.z, (v3.y + bA.w) * cv.y * h0.w);
                red_add_v4(dp + 4, (v4.y + bB.x) * cv.y * h1.x, (v5.y + bB.y) * cv.y * h1.y,
                                   (v6.y + bB.z) * cv.y * h1.z, (v7.y + bB.w) * cv.y * h1.w);
            }
        }
    }
}

// -------- Kernel 3: out = ssp(agg@lin2_w + lin2_b) @ lin_w + lin_b (R5 shape) --------
extern "C" __global__ void __launch_bounds__(512, 1)
k_out(const float* __restrict__ w2, const float* __restrict__ b2,
      const float* __restrict__ w3, const float* __restrict__ b3,
      float* __restrict__ out) {
    extern __shared__ float sm[];
    float* sW2 = sm;                  // 128*128 (lin2_w)
    float* sW3 = sW2 + DNF * DHID;    // 128*128 (lin_w)
    float* sA  = sW3 + DHID * DHID;   // 128*130 (aliased A then T)
    float* sB2 = sA + DNF * 130;      // 128
    float* sB3 = sB2 + 128;           // 128

    const int tid = threadIdx.x;
    const int rg = tid & 31, cg = tid >> 5;
    const int c0 = cg * 8;

    for (int i = tid; i < DNF * DHID / 4; i += 512)
        ((float4*)sW2)[i] = ((const float4*)w2)[i];
    for (int i = tid; i < DHID * DHID / 4; i += 512)
        ((float4*)sW3)[i] = ((const float4*)w3)[i];
    if (tid < DHID) { sB2[tid] = b2[tid]; sB3[tid] = b3[tid]; }

    const int ntiles = (NNODES + 127) / 128;
    for (int tile = blockIdx.x; tile < ntiles; tile += gridDim.x) {
        const int r0 = tile * 128;
        __syncthreads();
        {
            int e = tid >> 2, k0 = (tid & 3) << 5;
            int r = r0 + e;
            const float* src = g_agg + (size_t)r * DNF + k0;
#pragma unroll
            for (int i = 0; i < 8; ++i) {
                float4 v = (r < NNODES) ? ldcs4(src + 4 * i) : make_float4(0.f, 0.f, 0.f, 0.f);
                int k = k0 + 4 * i;
                sA[(k + 0) * 130 + e] = v.x;
                sA[(k + 1) * 130 + e] = v.y;
                sA[(k + 2) * 130 + e] = v.z;
                sA[(k + 3) * 130 + e] = v.w;
            }
        }
        __syncthreads();

        ull acc[4][4];
#pragma unroll
        for (int j = 0; j < 4; ++j)
#pragma unroll
            for (int p = 0; p < 4; ++p) acc[j][p] = 0ull;
        mm4x8<DNF>(sA, sW2, rg, c0, acc);
        __syncthreads();   // all reads of sA done before overwrite as T

#pragma unroll
        for (int p = 0; p < 4; ++p) {
            float bx = sB2[c0 + 2 * p], by = sB2[c0 + 2 * p + 1];
#pragma unroll
            for (int j = 0; j < 4; ++j) {
                float2 v = unpack2(acc[j][p]);
                int row = rg + 32 * j;
                sA[(c0 + 2 * p) * 130 + row] = ssp_f(v.x + bx);
                sA[(c0 + 2 * p + 1) * 130 + row] = ssp_f(v.y + by);
            }
        }
        __syncthreads();

#pragma unroll
        for (int j = 0; j < 4; ++j)
#pragma unroll
            for (int p = 0; p < 4; ++p) acc[j][p] = 0ull;
        mm4x8<DHID>(sA, sW3, rg, c0, acc);

#pragma unroll
        for (int j = 0; j < 4; ++j) {
            int r = r0 + rg + 32 * j;
            if (r < NNODES) {
                float2 v0 = unpack2(acc[j][0]), v1 = unpack2(acc[j][1]);
                float2 v2 = unpack2(acc[j][2]), v3 = unpack2(acc[j][3]);
                *(float4*)(out + (size_t)r * DHID + c0) =
                    make_float4(v0.x + sB3[c0 + 0], v0.y + sB3[c0 + 1],
                                v1.x + sB3[c0 + 2], v1.y + sB3[c0 + 3]);
                *(float4*)(out + (size_t)r * DHID + c0 + 4) =
                    make_float4(v2.x + sB3[c0 + 4], v2.y + sB3[c0 + 5],
                                v3.x + sB3[c0 + 6], v3.y + sB3[c0 + 7]);
            }
        }
    }
}

extern "C" void kernel_launch(void* const* d_in, const int* in_sizes, int n_in,
                              void* d_out, int out_size) {
    const float* x      = (const float*)d_in[0];
    const int*   ei     = (const int*)d_in[1];
    const float* elen   = (const float*)d_in[2];
    const float* eattr  = (const float*)d_in[3];
    const float* lin1_w = (const float*)d_in[4];
    const float* nn_w1  = (const float*)d_in[5];
    const float* nn_b1  = (const float*)d_in[6];
    const float* nn_w2  = (const float*)d_in[7];
    const float* nn_b2  = (const float*)d_in[8];
    const float* lin2_w = (const float*)d_in[9];
    const float* lin2_b = (const float*)d_in[10];
    const float* lin_w  = (const float*)d_in[11];
    const float* lin_b  = (const float*)d_in[12];
    float* out = (float*)d_out;

    size_t sm1 = (size_t)(DHID * 130) * 4;                            // 66560
    size_t sm2 = (size_t)(DNF * 130) * 4;                             // 66560
    size_t sm3 = (size_t)(DNF * DHID + DHID * DHID + DNF * 130 + 2 * 128) * 4;

    cudaFuncSetAttribute(k_proj_zero, cudaFuncAttributeMaxDynamicSharedMemorySize, (int)sm1);
    cudaFuncSetAttribute(k_edge, cudaFuncAttributeMaxDynamicSharedMemorySize, (int)sm2);
    cudaFuncSetAttribute(k_out, cudaFuncAttributeMaxDynamicSharedMemorySize, (int)sm3);

    k_proj_zero<<<304, 256, sm1>>>(x, lin1_w);          // also zeroes g_cnt + g_agg
    k_compact<<<152, 256>>>(ei, elen);
    k_edge<<<304, 256, sm2>>>(eattr, nn_w1, nn_b1, nn_w2, nn_b2);
    k_out<<<152, 512, sm3>>>(lin2_w, lin2_b, lin_w, lin_b, out);
}